// round 6
// baseline (speedup 1.0000x reference)
#include <cuda_runtime.h>
#include <cuda_bf16.h>

// AMSoftmaxLoss: score (2048 x 50257) fp32, labels (2048) int32 in {0,1}
// Warp-autonomous work stealing: 9472 warps pull 65536 row-segment tiles
// off a global ticket; no block barriers in the hot loop. Last block
// folds partials + epilogue.

#define NROWS 2048
#define CCOLS 50257
#define NBLK  1184            // 148 SMs * 8 resident blocks
#define BLK   256
#define SEGS  32
#define SEGW  1571            // 32*1571 = 50272 >= 50257 (last seg = 1556)
#define NTILES (NROWS * SEGS) // 65536

__device__ float g_part[NTILES];
__device__ int g_ticket = 0;           // reset by finalize block each launch
__device__ unsigned int g_count = 0;   // self-resetting via atomicInc wrap

__device__ __forceinline__ float ex2f(float x) {
    float y;
    asm("ex2.approx.ftz.f32 %0, %1;" : "=f"(y) : "f"(x));
    return y;
}

#define SL2E (30.0f * 1.44269504088896340736f)   // S * log2(e)

__global__ __launch_bounds__(BLK) void amsm_kernel(
    const float* __restrict__ score,
    const int* __restrict__ labels,
    float* __restrict__ out)
{
    const int tid  = threadIdx.x;
    const int lane = tid & 31;

    // ---- warp-autonomous ticket loop (no block barriers) ----
    int t = 0;
    if (lane == 0) t = atomicAdd(&g_ticket, 1);
    t = __shfl_sync(0xFFFFFFFFu, t, 0);

    while (t < NTILES) {
        int tn = 0;
        if (lane == 0) tn = atomicAdd(&g_ticket, 1);   // prefetch next ticket

        const int r    = t >> 5;
        const int seg  = t & 31;
        const int col0 = seg * SEGW;
        const int len  = (seg == SEGS - 1) ? (CCOLS - col0) : SEGW;
        const float* __restrict__ p = score + (size_t)r * CCOLS + col0;

        float s0 = 0.f, s1 = 0.f, s2 = 0.f, s3 = 0.f;

        int peel = (-(int)(((size_t)r * CCOLS + col0))) & 3;   // to 16B align
        if (peel > len) peel = len;
        if (lane < peel) s0 += ex2f(SL2E * p[lane]);

        const int n4 = (len - peel) >> 2;
        const float4* __restrict__ q = (const float4*)(p + peel);

        int i = lane;
        for (; i + 32 < n4; i += 64) {                 // 2 LDG.128 in flight
            float4 a = __ldcs(q + i);
            float4 b = __ldcs(q + i + 32);
            s0 += ex2f(SL2E * a.x); s1 += ex2f(SL2E * a.y);
            s2 += ex2f(SL2E * a.z); s3 += ex2f(SL2E * a.w);
            s0 += ex2f(SL2E * b.x); s1 += ex2f(SL2E * b.y);
            s2 += ex2f(SL2E * b.z); s3 += ex2f(SL2E * b.w);
        }
        for (; i < n4; i += 32) {
            float4 a = __ldcs(q + i);
            s0 += ex2f(SL2E * a.x); s1 += ex2f(SL2E * a.y);
            s2 += ex2f(SL2E * a.z); s3 += ex2f(SL2E * a.w);
        }
        const int done = peel + 4 * n4;
        if (lane < len - done) s0 += ex2f(SL2E * p[done + lane]);

        float v = (s0 + s1) + (s2 + s3);
        #pragma unroll
        for (int off = 16; off > 0; off >>= 1)
            v += __shfl_down_sync(0xFFFFFFFFu, v, off);
        if (lane == 0) g_part[t] = v;

        t = __shfl_sync(0xFFFFFFFFu, tn, 0);
    }

    // ---- block completion, then last-arriving block finalizes ----
    __syncthreads();
    __shared__ unsigned s_last;
    if (tid == 0) {
        __threadfence();
        unsigned old = atomicInc(&g_count, NBLK - 1);   // wraps -> self-reset
        s_last = (old == NBLK - 1) ? 1u : 0u;
    }
    __syncthreads();
    if (!s_last) return;

    if (tid == 0) g_ticket = 0;            // clean for next graph replay

    volatile float* gp = g_part;
    double acc = 0.0;
    for (int r = tid; r < NROWS; r += BLK) {
        float rs = 0.f;
        #pragma unroll
        for (int k = 0; k < SEGS; k++) rs += gp[r * SEGS + k];

        int lab = labels[r] & 1;
        float m = lab ? 0.4f : 0.1f;
        float tg = __ldg(score + (size_t)r * CCOLS + lab);
        float num = 30.0f * (tg - m);
        float excl = rs - ex2f(SL2E * tg);
        float denom = ex2f(num * 1.44269504088896340736f) + excl;
        acc += (double)(num - logf(denom));
    }

    __shared__ double dred[BLK];
    dred[tid] = acc;
    __syncthreads();
    #pragma unroll
    for (int off = BLK / 2; off > 0; off >>= 1) {
        if (tid < off) dred[tid] += dred[tid + off];
        __syncthreads();
    }
    if (tid == 0)
        out[0] = (float)(-dred[0] / (double)NROWS);
}

extern "C" void kernel_launch(void* const* d_in, const int* in_sizes, int n_in,
                              void* d_out, int out_size)
{
    const float* score = (const float*)d_in[0];
    const int* labels = (const int*)d_in[1];
    float* out = (float*)d_out;

    amsm_kernel<<<NBLK, BLK>>>(score, labels, out);
}

// round 7
// speedup vs baseline: 1.8780x; 1.8780x over previous
#include <cuda_runtime.h>
#include <cuda_bf16.h>

// AMSoftmaxLoss: score (2048 x 50257) fp32, labels (2048) int32 in {0,1}
// 16384 short HW-scheduled blocks (8 segments per row) -> continuous
// backfill, no wave quantization, no software ticket. Last-arriving
// block folds partials + epilogue.

#define NROWS 2048
#define CCOLS 50257
#define BLK   256
#define SEGS  8
#define SEGW  6283            // 8*6283 = 50264 >= 50257 (last seg = 6276)
#define NTILES (NROWS * SEGS) // 16384

__device__ float g_part[NTILES];
__device__ unsigned int g_count = 0;   // self-resetting via atomicInc wrap

__device__ __forceinline__ float ex2f(float x) {
    float y;
    asm("ex2.approx.ftz.f32 %0, %1;" : "=f"(y) : "f"(x));
    return y;
}

#define SL2E (30.0f * 1.44269504088896340736f)   // S * log2(e)

__global__ __launch_bounds__(BLK) void amsm_kernel(
    const float* __restrict__ score,
    const int* __restrict__ labels,
    float* __restrict__ out)
{
    const int t    = blockIdx.x;
    const int tid  = threadIdx.x;
    const int lane = tid & 31;
    const int wid  = tid >> 5;

    const int r    = t >> 3;
    const int seg  = t & 7;
    const int col0 = seg * SEGW;
    const int len  = (seg == SEGS - 1) ? (CCOLS - col0) : SEGW;
    const float* __restrict__ p = score + (size_t)r * CCOLS + col0;

    float s0 = 0.f, s1 = 0.f, s2 = 0.f, s3 = 0.f;

    int peel = (-(int)((unsigned)(r * CCOLS + col0))) & 3;     // to 16B align
    if (peel > len) peel = len;
    if (tid < peel) s0 += ex2f(SL2E * p[tid]);

    const int n4 = (len - peel) >> 2;
    const float4* __restrict__ q = (const float4*)(p + peel);

    int i = tid;
    for (; i + BLK < n4; i += 2 * BLK) {                 // 2 LDG.128 in flight
        float4 a = __ldcs(q + i);
        float4 b = __ldcs(q + i + BLK);
        s0 += ex2f(SL2E * a.x); s1 += ex2f(SL2E * a.y);
        s2 += ex2f(SL2E * a.z); s3 += ex2f(SL2E * a.w);
        s0 += ex2f(SL2E * b.x); s1 += ex2f(SL2E * b.y);
        s2 += ex2f(SL2E * b.z); s3 += ex2f(SL2E * b.w);
    }
    for (; i < n4; i += BLK) {
        float4 a = __ldcs(q + i);
        s0 += ex2f(SL2E * a.x); s1 += ex2f(SL2E * a.y);
        s2 += ex2f(SL2E * a.z); s3 += ex2f(SL2E * a.w);
    }
    const int done = peel + 4 * n4;
    if (tid < len - done) s0 += ex2f(SL2E * p[done + tid]);

    float v = (s0 + s1) + (s2 + s3);

    // Block reduction: warp shuffle then cross-warp via smem.
    __shared__ float wsum[BLK / 32];
    #pragma unroll
    for (int off = 16; off > 0; off >>= 1)
        v += __shfl_down_sync(0xFFFFFFFFu, v, off);
    if (lane == 0) wsum[wid] = v;
    __syncthreads();

    __shared__ unsigned s_last;
    if (tid == 0) {
        float w = 0.f;
        #pragma unroll
        for (int k = 0; k < BLK / 32; k++) w += wsum[k];
        g_part[t] = w;
        __threadfence();
        unsigned old = atomicInc(&g_count, NTILES - 1);  // wraps -> self-reset
        s_last = (old == NTILES - 1) ? 1u : 0u;
    }
    __syncthreads();
    if (!s_last) return;

    // ---- Last-arriving block: fold partials, per-row epilogue, mean ----
    volatile float* gp = g_part;
    double acc = 0.0;
    for (int r2 = tid; r2 < NROWS; r2 += BLK) {
        float rs = 0.f;
        #pragma unroll
        for (int k = 0; k < SEGS; k++) rs += gp[r2 * SEGS + k];

        int lab = labels[r2] & 1;
        float m = lab ? 0.4f : 0.1f;
        float tg = __ldg(score + (size_t)r2 * CCOLS + lab);
        float num = 30.0f * (tg - m);
        float excl = rs - ex2f(SL2E * tg);
        float denom = ex2f(num * 1.44269504088896340736f) + excl;
        acc += (double)(num - logf(denom));
    }

    __shared__ double dred[BLK];
    dred[tid] = acc;
    __syncthreads();
    #pragma unroll
    for (int off = BLK / 2; off > 0; off >>= 1) {
        if (tid < off) dred[tid] += dred[tid + off];
        __syncthreads();
    }
    if (tid == 0)
        out[0] = (float)(-dred[0] / (double)NROWS);
}

extern "C" void kernel_launch(void* const* d_in, const int* in_sizes, int n_in,
                              void* d_out, int out_size)
{
    const float* score = (const float*)d_in[0];
    const int* labels = (const int*)d_in[1];
    float* out = (float*)d_out;

    amsm_kernel<<<NTILES, BLK>>>(score, labels, out);
}

// round 8
// speedup vs baseline: 1.9195x; 1.0221x over previous
#include <cuda_runtime.h>
#include <cuda_bf16.h>

// AMSoftmaxLoss: score (2048 x 50257) fp32, labels (2048) int32 in {0,1}
// Persistent 1184 blocks; block-level prefetched ticket over 4096 half-row
// tiles (~25K elems). One __syncthreads per tile; per-warp partials (tile is
// within a single row) -> no block reduction. Last block folds + epilogue.

#define NROWS 2048
#define CCOLS 50257
#define NBLK  1184            // 148 SMs * 8 resident blocks
#define BLK   256
#define NW    (BLK / 32)      // 8 warps
#define SEGS  2
#define SEGW  25132           // seg0 = 25132, seg1 = 25125; same mod-4 class
#define NTILES (NROWS * SEGS) // 4096

__device__ float g_part[NTILES * NW];
__device__ int g_ticket = 0;           // reset by finalize block each launch
__device__ unsigned int g_count = 0;   // self-resetting via atomicInc wrap

__device__ __forceinline__ float ex2f(float x) {
    float y;
    asm("ex2.approx.ftz.f32 %0, %1;" : "=f"(y) : "f"(x));
    return y;
}

#define SL2E (30.0f * 1.44269504088896340736f)   // S * log2(e)

__global__ __launch_bounds__(BLK) void amsm_kernel(
    const float* __restrict__ score,
    const int* __restrict__ labels,
    float* __restrict__ out)
{
    const int tid  = threadIdx.x;
    const int lane = tid & 31;
    const int wid  = tid >> 5;

    __shared__ int s_tile[2];

    if (tid == 0) s_tile[0] = atomicAdd(&g_ticket, 1);
    __syncthreads();
    int buf = 0;
    int t = s_tile[0];

    while (t < NTILES) {
        int tn = 0;
        if (tid == 0) tn = atomicAdd(&g_ticket, 1);    // prefetch next ticket

        const int r    = t >> 1;
        const int seg  = t & 1;
        const int col0 = seg * SEGW;
        const int len  = seg ? (CCOLS - SEGW) : SEGW;
        const float* __restrict__ p = score + (size_t)r * CCOLS + col0;

        float s0 = 0.f, s1 = 0.f, s2 = 0.f, s3 = 0.f;

        int peel = (-(r * CCOLS + col0)) & 3;          // to 16B alignment
        if (tid < peel) s0 += ex2f(SL2E * p[tid]);

        const int n4 = (len - peel) >> 2;
        const float4* __restrict__ q = (const float4*)(p + peel);

        int i = tid;
        for (; i + 3 * BLK < n4; i += 4 * BLK) {       // 4 LDG.128 in flight
            float4 a = q[i];
            float4 b = q[i + BLK];
            float4 c = q[i + 2 * BLK];
            float4 d = q[i + 3 * BLK];
            s0 += ex2f(SL2E * a.x); s1 += ex2f(SL2E * a.y);
            s2 += ex2f(SL2E * a.z); s3 += ex2f(SL2E * a.w);
            s0 += ex2f(SL2E * b.x); s1 += ex2f(SL2E * b.y);
            s2 += ex2f(SL2E * b.z); s3 += ex2f(SL2E * b.w);
            s0 += ex2f(SL2E * c.x); s1 += ex2f(SL2E * c.y);
            s2 += ex2f(SL2E * c.z); s3 += ex2f(SL2E * c.w);
            s0 += ex2f(SL2E * d.x); s1 += ex2f(SL2E * d.y);
            s2 += ex2f(SL2E * d.z); s3 += ex2f(SL2E * d.w);
        }
        for (; i < n4; i += BLK) {
            float4 a = q[i];
            s0 += ex2f(SL2E * a.x); s1 += ex2f(SL2E * a.y);
            s2 += ex2f(SL2E * a.z); s3 += ex2f(SL2E * a.w);
        }
        const int done = peel + 4 * n4;
        if (tid < len - done) s0 += ex2f(SL2E * p[done + tid]);

        float v = (s0 + s1) + (s2 + s3);
        #pragma unroll
        for (int off = 16; off > 0; off >>= 1)
            v += __shfl_down_sync(0xFFFFFFFFu, v, off);
        if (lane == 0) g_part[t * NW + wid] = v;       // per-warp partial

        if (tid == 0) s_tile[buf ^ 1] = tn;
        __syncthreads();                               // one barrier per tile
        buf ^= 1;
        t = s_tile[buf];
    }

    // ---- completion; last-arriving block finalizes ----
    __syncthreads();
    __shared__ unsigned s_last;
    if (tid == 0) {
        __threadfence();
        unsigned old = atomicInc(&g_count, NBLK - 1);  // wraps -> self-reset
        s_last = (old == NBLK - 1) ? 1u : 0u;
    }
    __syncthreads();
    if (!s_last) return;

    if (tid == 0) g_ticket = 0;            // clean for next graph replay

    volatile float* gp = g_part;
    double acc = 0.0;
    for (int r = tid; r < NROWS; r += BLK) {
        float rs = 0.f;
        #pragma unroll
        for (int k = 0; k < SEGS * NW; k++)
            rs += gp[r * SEGS * NW + k];

        int lab = labels[r] & 1;
        float m = lab ? 0.4f : 0.1f;
        float tg = __ldg(score + (size_t)r * CCOLS + lab);
        float num = 30.0f * (tg - m);
        float excl = rs - ex2f(SL2E * tg);
        float denom = ex2f(num * 1.44269504088896340736f) + excl;
        acc += (double)(num - logf(denom));
    }

    __shared__ double dred[BLK];
    dred[tid] = acc;
    __syncthreads();
    #pragma unroll
    for (int off = BLK / 2; off > 0; off >>= 1) {
        if (tid < off) dred[tid] += dred[tid + off];
        __syncthreads();
    }
    if (tid == 0)
        out[0] = (float)(-dred[0] / (double)NROWS);
}

extern "C" void kernel_launch(void* const* d_in, const int* in_sizes, int n_in,
                              void* d_out, int out_size)
{
    const float* score = (const float*)d_in[0];
    const int* labels = (const int*)d_in[1];
    float* out = (float*)d_out;

    amsm_kernel<<<NBLK, BLK>>>(score, labels, out);
}